// round 16
// baseline (speedup 1.0000x reference)
#include <cuda_runtime.h>

#define B_  32
#define G_  256
#define P_  2048
#define NC_ 80

#define THREADS_  512
#define CHUNKS_   4                     // blocks per batch
#define PRED_BLK_ (P_ / CHUNKS_)        // 512 preds per block == 1 per thread
#define NBLOCKS_  (CHUNKS_ * B_)        // 128 blocks -> single wave

#define NREP_ 4                         // phist replicas (cut smem-atomic contention)

__device__ double   g_sum;              // zero at load; reset by last block each run
__device__ unsigned g_done;

__global__ void __launch_bounds__(THREADS_)
fused_giou_kernel(const float* __restrict__ imgs_box,
                  const int*   __restrict__ img_labels,
                  const float* __restrict__ pre_BOX,
                  const int*   __restrict__ pre_label,
                  float*       __restrict__ out)
{
    const int b     = blockIdx.y;
    const int chunk = blockIdx.x;
    const int tid   = threadIdx.x;
    const int wid   = tid >> 5, lid = tid & 31;

    __shared__ float4 s_box[G_];            // GT boxes, class-grouped
    __shared__ int    s_gidx[G_];           // original g index, class-grouped
    __shared__ int    s_hist[NC_];          // class counts; reused as scatter down-counter
    __shared__ int    s_off[NC_ + 1];       // per-SEGMENT-local exclusive prefix
    __shared__ int    s_T[3];               // segment totals
    __shared__ int    s_phist4[NREP_ * NC_];// replicated pre_label histograms
    __shared__ int    s_phist[NC_];         // final weights
    __shared__ float  s_wsum[16];

    // ---- prefetch ALL global data before any barrier.
    //      GT loads ISSUED FIRST: they gate the staging phases; pred data is
    //      not consumed until 3 barriers later, so its latency hides anyway. ----
    int    mylab = 0;
    float4 mybox = make_float4(0.f, 0.f, 0.f, 0.f);
    if (tid < G_) {
        mylab = img_labels[b * G_ + tid];
        mybox = reinterpret_cast<const float4*>(imgs_box)[b * G_ + tid];
    }
    const int4   pls  = reinterpret_cast<const int4*>(pre_label + b * P_)[tid]; // 512*4 = 2048
    const int    p    = chunk * PRED_BLK_ + tid;
    const float4 pb   = reinterpret_cast<const float4*>(pre_BOX)[b * P_ + p];
    const int    plab = pre_label[b * P_ + p];

    // ---- pred-side math hoisted (overlaps barrier phases) ----
    // boxes satisfy x2 = x1 + wh with wh >= 1, so widths are always positive:
    // the reference's clip-at-0 on pw/ph is a provable no-op (verified R11/R12,
    // rel_err unchanged at 9.0e-8).
    const float pw  = pb.z - pb.x + 1.0f;
    const float ph  = pb.w - pb.y + 1.0f;
    const float pa  = pw * ph;
    const float rpa = __fdividef(1.0f, pa);

    // ---- zeroing over disjoint thread ranges (one store per thread) ----
    if (tid < NREP_ * NC_)                  s_phist4[tid] = 0;              // 0..319
    else if (tid < NREP_ * NC_ + NC_)       s_hist[tid - NREP_ * NC_] = 0;  // 320..399
    __syncthreads();

    // ---- histograms (replica wid&3 cuts contention ~4x) ----
    if (tid < G_) atomicAdd(&s_hist[mylab], 1);
    {
        int* rep = &s_phist4[(wid & (NREP_ - 1)) * NC_];
        atomicAdd(&rep[pls.x], 1);
        atomicAdd(&rep[pls.y], 1);
        atomicAdd(&rep[pls.z], 1);
        atomicAdd(&rep[pls.w], 1);
    }
    __syncthreads();

    // ---- concurrent: warps 0..2 segmented prefix; threads 96..175 fold replicas ----
    if (wid < 3) {
        const int idx = (wid << 5) + lid;
        const int h   = (idx < NC_) ? s_hist[idx] : 0;
        int v = h;
        #pragma unroll
        for (int off = 1; off < 32; off <<= 1) {
            const int n = __shfl_up_sync(0xFFFFFFFFu, v, off);
            if (lid >= off) v += n;
        }
        if (idx < NC_) s_off[idx] = v - h;          // segment-LOCAL exclusive
        if (lid == 31) {
            s_T[wid] = v;
            if (wid == 2) s_off[NC_] = v;           // local value at idx==80
        }
    } else if (tid >= 96 && tid < 96 + NC_) {
        const int c = tid - 96;
        s_phist[c] = s_phist4[c] + s_phist4[NC_ + c]
                   + s_phist4[2 * NC_ + c] + s_phist4[3 * NC_ + c];
    }
    __syncthreads();

    const int t0  = s_T[0];
    const int t01 = t0 + s_T[1];

    // ---- scatter GT into class-grouped arrays (s_hist as down-counter) ----
    if (tid < G_) {
        const int seg  = mylab >> 5;
        const int base = (seg == 0) ? 0 : ((seg == 1) ? t0 : t01);
        const int v    = atomicSub(&s_hist[mylab], 1);   // old count >= 1
        const int pos  = base + s_off[mylab] + v - 1;
        s_box[pos]  = mybox;
        s_gidx[pos] = tid;
    }
    __syncthreads();

    // ---- score one prediction per thread ----
    const int segA  = plab >> 5;
    const int baseA = (segA == 0) ? 0 : ((segA == 1) ? t0 : t01);
    const int segB  = (plab + 1) >> 5;
    const int baseB = (segB == 0) ? 0 : ((segB == 1) ? t0 : t01);
    const int start = baseA + s_off[plab];
    const int end   = baseB + s_off[plab + 1];

    // weight LDS hoisted above the loop: latency hides under the scan
    const float wgt = (float)s_phist[plab];

    int   best_g    = -1;
    float best_giou = 0.0f;

    #pragma unroll 2
    for (int i = start; i < end; ++i) {
        const int    g  = s_gidx[i];     // issue index load first (deeper LDS MLP)
        const float4 tb = s_box[i];

        // tw/th always positive: no clamp (see note above).
        const float tw = tb.z - tb.x + 1.0f;
        const float th = tb.w - tb.y + 1.0f;
        const float ta = tw * th;

        const float iw = fmaxf(fminf(pb.z, tb.z) - fmaxf(pb.x, tb.x) + 1.0f, 0.0f);
        const float ih = fmaxf(fminf(pb.w, tb.w) - fmaxf(pb.y, tb.y) + 1.0f, 0.0f);
        const float inter = iw * ih;
        const float uni   = pa + ta - inter;

        const float iou = fmaxf(inter * rpa, 1e-6f);     // reference: / pred area

        // outer dims always positive: no clamp.
        const float ow = fmaxf(pb.z, tb.z) - fminf(pb.x, tb.x) + 1.0f;
        const float oh = fmaxf(pb.w, tb.w) - fminf(pb.y, tb.y) + 1.0f;
        const float outer = ow * oh;

        // giou in (-1, 1] mathematically: reference clip is a no-op.
        const float giou = iou - __fdividef(outer - uni, outer);

        if (giou > 0.0f && g > best_g) { best_g = g; best_giou = giou; }
    }

    float acc = (best_g >= 0) ? (1.0f - best_giou) * wgt : 0.0f;

    // ---- block reduction (16 warps) ----
    #pragma unroll
    for (int off = 16; off > 0; off >>= 1)
        acc += __shfl_down_sync(0xFFFFFFFFu, acc, off);

    if (lid == 0) s_wsum[wid] = acc;
    __syncthreads();
    if (tid < 32) {
        float v = (tid < 16) ? s_wsum[tid] : 0.0f;
        #pragma unroll
        for (int off = 8; off > 0; off >>= 1)
            v += __shfl_down_sync(0xFFFFFFFFu, v, off);
        if (tid == 0) {
            atomicAdd(&g_sum, (double)v);       // one RED per block
            __threadfence();
            const unsigned t = atomicAdd(&g_done, 1u);
            if (t == NBLOCKS_ - 1u) {
                const double total = *((volatile double*)&g_sum);
                *out = (float)(total / (double)B_);
                g_sum = 0.0;                    // reset for next graph replay
                __threadfence();
                g_done = 0u;
            }
        }
    }
}

extern "C" void kernel_launch(void* const* d_in, const int* in_sizes, int n_in,
                              void* d_out, int out_size)
{
    const float* imgs_box   = (const float*)d_in[0];
    const int*   img_labels = (const int*)  d_in[1];
    const float* pre_BOX    = (const float*)d_in[2];
    const int*   pre_label  = (const int*)  d_in[3];
    float* out = (float*)d_out;

    dim3 grid(CHUNKS_, B_);
    fused_giou_kernel<<<grid, THREADS_>>>(imgs_box, img_labels, pre_BOX, pre_label, out);
}

// round 17
// speedup vs baseline: 1.0336x; 1.0336x over previous
#include <cuda_runtime.h>

#define B_  32
#define G_  256
#define P_  2048
#define NC_ 80

#define THREADS_  512
#define CHUNKS_   4                     // blocks per batch
#define PRED_BLK_ (P_ / CHUNKS_)        // 512 preds per block == 1 per thread
#define NBLOCKS_  (CHUNKS_ * B_)        // 128 blocks -> single wave

#define NREP_ 4                         // phist replicas (cut smem-atomic contention)

__device__ double   g_sum;              // zero at load; reset by last block each run
__device__ unsigned g_done;

__global__ void __launch_bounds__(THREADS_)
fused_giou_kernel(const float* __restrict__ imgs_box,
                  const int*   __restrict__ img_labels,
                  const float* __restrict__ pre_BOX,
                  const int*   __restrict__ pre_label,
                  float*       __restrict__ out)
{
    const int b     = blockIdx.y;
    const int chunk = blockIdx.x;
    const int tid   = threadIdx.x;
    const int wid   = tid >> 5, lid = tid & 31;

    __shared__ float4 s_box[G_];            // GT boxes, class-grouped
    __shared__ int    s_gidx[G_];           // original g index, class-grouped
    __shared__ int    s_hist[NC_];          // class counts; reused as scatter down-counter
    __shared__ int    s_off[NC_ + 1];       // per-SEGMENT-local exclusive prefix
    __shared__ int    s_T[3];               // segment totals
    __shared__ int    s_phist4[NREP_ * NC_];// replicated pre_label histograms
    __shared__ int    s_phist[NC_];         // final weights
    __shared__ float  s_wsum[16];

    // ---- prefetch ALL global data before any barrier ----
    const int p = chunk * PRED_BLK_ + tid;
    const float4 pb   = reinterpret_cast<const float4*>(pre_BOX)[b * P_ + p];
    const int    plab = pre_label[b * P_ + p];
    const int4   pls  = reinterpret_cast<const int4*>(pre_label + b * P_)[tid]; // 512*4 = 2048

    int    mylab = 0;
    float4 mybox = make_float4(0.f, 0.f, 0.f, 0.f);
    if (tid < G_) {
        mylab = img_labels[b * G_ + tid];
        mybox = reinterpret_cast<const float4*>(imgs_box)[b * G_ + tid];
    }

    // ---- pred-side math hoisted (overlaps barrier phases) ----
    // boxes satisfy x2 = x1 + wh with wh >= 1, so widths are always positive:
    // the reference's clip-at-0 on pw/ph is a provable no-op (verified R11/R12,
    // rel_err unchanged at 9.0e-8).
    const float pw  = pb.z - pb.x + 1.0f;
    const float ph  = pb.w - pb.y + 1.0f;
    const float pa  = pw * ph;
    const float rpa = __fdividef(1.0f, pa);

    // ---- zeroing over disjoint thread ranges (one store per thread) ----
    if (tid < NREP_ * NC_)                  s_phist4[tid] = 0;              // 0..319
    else if (tid < NREP_ * NC_ + NC_)       s_hist[tid - NREP_ * NC_] = 0;  // 320..399
    __syncthreads();

    // ---- histograms (replica wid&3 cuts contention ~4x) ----
    if (tid < G_) atomicAdd(&s_hist[mylab], 1);
    {
        int* rep = &s_phist4[(wid & (NREP_ - 1)) * NC_];
        atomicAdd(&rep[pls.x], 1);
        atomicAdd(&rep[pls.y], 1);
        atomicAdd(&rep[pls.z], 1);
        atomicAdd(&rep[pls.w], 1);
    }
    __syncthreads();

    // ---- concurrent: warps 0..2 segmented prefix; threads 96..175 fold replicas ----
    if (wid < 3) {
        const int idx = (wid << 5) + lid;
        const int h   = (idx < NC_) ? s_hist[idx] : 0;
        int v = h;
        #pragma unroll
        for (int off = 1; off < 32; off <<= 1) {
            const int n = __shfl_up_sync(0xFFFFFFFFu, v, off);
            if (lid >= off) v += n;
        }
        if (idx < NC_) s_off[idx] = v - h;          // segment-LOCAL exclusive
        if (lid == 31) {
            s_T[wid] = v;
            if (wid == 2) s_off[NC_] = v;           // local value at idx==80
        }
    } else if (tid >= 96 && tid < 96 + NC_) {
        const int c = tid - 96;
        s_phist[c] = s_phist4[c] + s_phist4[NC_ + c]
                   + s_phist4[2 * NC_ + c] + s_phist4[3 * NC_ + c];
    }
    __syncthreads();

    const int t0  = s_T[0];
    const int t01 = t0 + s_T[1];

    // ---- scatter GT into class-grouped arrays (s_hist as down-counter) ----
    if (tid < G_) {
        const int seg  = mylab >> 5;
        const int base = (seg == 0) ? 0 : ((seg == 1) ? t0 : t01);
        const int v    = atomicSub(&s_hist[mylab], 1);   // old count >= 1
        const int pos  = base + s_off[mylab] + v - 1;
        s_box[pos]  = mybox;
        s_gidx[pos] = tid;
    }
    __syncthreads();

    // ---- score one prediction per thread ----
    const int segA  = plab >> 5;
    const int baseA = (segA == 0) ? 0 : ((segA == 1) ? t0 : t01);
    const int segB  = (plab + 1) >> 5;
    const int baseB = (segB == 0) ? 0 : ((segB == 1) ? t0 : t01);
    const int start = baseA + s_off[plab];
    const int end   = baseB + s_off[plab + 1];

    int   best_g    = -1;
    float best_giou = 0.0f;

    #pragma unroll 2
    for (int i = start; i < end; ++i) {
        const int    g  = s_gidx[i];     // issue index load first (deeper LDS MLP)
        const float4 tb = s_box[i];

        // tw/th always positive: no clamp (see note above).
        const float tw = tb.z - tb.x + 1.0f;
        const float th = tb.w - tb.y + 1.0f;
        const float ta = tw * th;

        const float iw = fmaxf(fminf(pb.z, tb.z) - fmaxf(pb.x, tb.x) + 1.0f, 0.0f);
        const float ih = fmaxf(fminf(pb.w, tb.w) - fmaxf(pb.y, tb.y) + 1.0f, 0.0f);
        const float inter = iw * ih;
        const float uni   = pa + ta - inter;

        const float iou = fmaxf(inter * rpa, 1e-6f);     // reference: / pred area

        // outer dims always positive: no clamp.
        const float ow = fmaxf(pb.z, tb.z) - fminf(pb.x, tb.x) + 1.0f;
        const float oh = fmaxf(pb.w, tb.w) - fminf(pb.y, tb.y) + 1.0f;
        const float outer = ow * oh;

        // giou in (-1, 1] mathematically: reference clip is a no-op.
        const float giou = iou - __fdividef(outer - uni, outer);

        if (giou > 0.0f && g > best_g) { best_g = g; best_giou = giou; }
    }

    float acc = (best_g >= 0) ? (1.0f - best_giou) * (float)s_phist[plab] : 0.0f;

    // ---- block reduction (16 warps) ----
    #pragma unroll
    for (int off = 16; off > 0; off >>= 1)
        acc += __shfl_down_sync(0xFFFFFFFFu, acc, off);

    if (lid == 0) s_wsum[wid] = acc;
    __syncthreads();
    if (tid < 32) {
        float v = (tid < 16) ? s_wsum[tid] : 0.0f;
        #pragma unroll
        for (int off = 8; off > 0; off >>= 1)
            v += __shfl_down_sync(0xFFFFFFFFu, v, off);
        if (tid == 0) {
            atomicAdd(&g_sum, (double)v);       // one RED per block
            __threadfence();
            const unsigned t = atomicAdd(&g_done, 1u);
            if (t == NBLOCKS_ - 1u) {
                const double total = *((volatile double*)&g_sum);
                *out = (float)(total / (double)B_);
                g_sum = 0.0;                    // reset for next graph replay
                __threadfence();
                g_done = 0u;
            }
        }
    }
}

extern "C" void kernel_launch(void* const* d_in, const int* in_sizes, int n_in,
                              void* d_out, int out_size)
{
    const float* imgs_box   = (const float*)d_in[0];
    const int*   img_labels = (const int*)  d_in[1];
    const float* pre_BOX    = (const float*)d_in[2];
    const int*   pre_label  = (const int*)  d_in[3];
    float* out = (float*)d_out;

    dim3 grid(CHUNKS_, B_);
    fused_giou_kernel<<<grid, THREADS_>>>(imgs_box, img_labels, pre_BOX, pre_label, out);
}